// round 12
// baseline (speedup 1.0000x reference)
#include <cuda_runtime.h>
#include <math.h>

#define NT 64
#define NH 2048
#define NI 1408
#define NE 32
#define NK 4
#define NPAIR (NT * NK)
#define MAXSLOT (NPAIR + NE)   // per-expert even padding adds <=1 slot each

// ---- scratch (device globals: no allocation allowed) ----
__device__ int   d_expert_count[NE];
__device__ int   d_expert_start[NE];     // even per-expert starts
__device__ int   d_total_slots;
__device__ int   d_pair_token[MAXSLOT];          // slot -> token (pads -> 0)
__device__ int   d_pair_idx[NT * NK];            // (token,k) -> slot
__device__ float d_topk_w[NT * NK];              // routing weights
__device__ float d_xg2[(MAXSLOT + 2) * NH];      // x, token-PAIR interleaved: [g][k][2]
__device__ float d_mixed2[(MAXSLOT + 2) * NI];   // silu(g)*u, same interleaving
__device__ float d_pair_out[MAXSLOT * NH];       // down output per slot

// ---- packed f32x2 helpers (FFMA2: PTX-only on sm_103a) ----
__device__ __forceinline__ unsigned long long pk2(float lo, float hi) {
    unsigned long long r;
    asm("mov.b64 %0, {%1, %2};" : "=l"(r) : "f"(lo), "f"(hi));
    return r;
}
__device__ __forceinline__ void upk2(unsigned long long v, float& lo, float& hi) {
    asm("mov.b64 {%0, %1}, %2;" : "=f"(lo), "=f"(hi) : "l"(v));
}
__device__ __forceinline__ unsigned long long fma2(unsigned long long a,
                                                   unsigned long long b,
                                                   unsigned long long c) {
    unsigned long long d;
    asm("fma.rn.f32x2 %0, %1, %2, %3;" : "=l"(d) : "l"(a), "l"(b), "l"(c));
    return d;
}
__device__ __forceinline__ unsigned long long add2(unsigned long long a,
                                                   unsigned long long b) {
    unsigned long long d;
    asm("add.rn.f32x2 %0, %1, %2;" : "=l"(d) : "l"(a), "l"(b));
    return d;
}

// ============================================================
// Kernel 1: routing. One block, one thread per token.
// ============================================================
__global__ void route_kernel(const float* __restrict__ logits) {
    __shared__ int s_count[NE];
    __shared__ int s_start[NE];
    __shared__ int s_slot[NE];
    const int t = threadIdx.x;

    if (t < NE) { s_count[t] = 0; s_slot[t] = 0; }
    __syncthreads();

    float v[NE];
#pragma unroll
    for (int e = 0; e < NE; e++) v[e] = logits[t * NE + e];

    int ids[NK];
    float vals[NK];
#pragma unroll
    for (int k = 0; k < NK; k++) {
        int best = 0;
        float bv = -1e30f;
#pragma unroll
        for (int e = 0; e < NE; e++) {
            if (v[e] > bv) { bv = v[e]; best = e; }  // strict > : lowest index wins ties
        }
        ids[k] = best;
        vals[k] = bv;
        v[best] = -1e30f;
    }

    float m = vals[0];
    float w[NK];
    float s = 0.f;
#pragma unroll
    for (int k = 0; k < NK; k++) { w[k] = expf(vals[k] - m); s += w[k]; }
    float inv = 1.f / s;
#pragma unroll
    for (int k = 0; k < NK; k++) d_topk_w[t * NK + k] = w[k] * inv;

#pragma unroll
    for (int k = 0; k < NK; k++) atomicAdd(&s_count[ids[k]], 1);
    __syncthreads();

    if (t == 0) {
        int off = 0;
        for (int e = 0; e < NE; e++) {
            s_start[e] = off;
            off += (s_count[e] + 1) & ~1;   // pad each expert region to even
        }
        d_total_slots = off;
    }
    __syncthreads();

#pragma unroll
    for (int k = 0; k < NK; k++) {
        int slot = atomicAdd(&s_slot[ids[k]], 1);
        int p = s_start[ids[k]] + slot;
        d_pair_token[p] = t;
        d_pair_idx[t * NK + k] = p;
    }
    if (t < NE) {
        d_expert_count[t] = s_count[t];
        d_expert_start[t] = s_start[t];
        if (s_count[t] & 1)                  // fill the pad slot with token 0
            d_pair_token[s_start[t] + s_count[t]] = 0;
    }
}

// ============================================================
// Kernel 1b: gather x rows, token-pair interleaved.
//   d_xg2[(p&~1)*NH + 2k + (p&1)] = x[token(p)][k]
// ============================================================
__global__ void gather_kernel(const float* __restrict__ x) {
    const int p = blockIdx.x;
    if (p >= d_total_slots) return;
    const int t = d_pair_token[p];
    const int g = p & ~1;
    const int par = p & 1;
    const float* __restrict__ src = x + (size_t)t * NH;
    float* __restrict__ dst = d_xg2 + (size_t)g * NH + par;
    for (int k = threadIdx.x; k < NH; k += blockDim.x)
        dst[2 * k] = src[k];
}

// ============================================================
// Kernel 2: gate/up matvecs + SiLU. One warp: 2 inter rows
// (gate+up = 4 weight streams), P token-pairs in FFMA2 halves.
// Per-lane granularity = 2 k-values -> ALL loads stride-dense:
// weights float2 (2 lines/instr), pairs ulonglong2 (4 lines).
// ============================================================
template<int P>   // token pairs this pass, 1..4
__device__ __forceinline__ void gateup_body(
    const int nc, const int slot0,
    const float2* __restrict__ G0, const float2* __restrict__ G1,
    const float2* __restrict__ U0, const float2* __restrict__ U1,
    const int i0, const int lane)
{
    constexpr int ITERS = NH / 2 / 32;   // 32

    unsigned long long ag0[P], ag1[P], au0[P], au1[P];
#pragma unroll
    for (int p = 0; p < P; p++) { ag0[p] = 0ull; ag1[p] = 0ull; au0[p] = 0ull; au1[p] = 0ull; }

    const ulonglong2* __restrict__ xp[P];
#pragma unroll
    for (int p = 0; p < P; p++)
        xp[p] = (const ulonglong2*)(d_xg2 + (size_t)(slot0 + 2 * p) * NH);

#pragma unroll 4
    for (int it = 0; it < ITERS; it++) {
        const int kq = lane + 32 * it;       // covers k = 2kq, 2kq+1
        const float2 a0 = __ldg(&G0[kq]);
        const float2 a1 = __ldg(&G1[kq]);
        const float2 b0 = __ldg(&U0[kq]);
        const float2 b1 = __ldg(&U1[kq]);
        const unsigned long long A0x = pk2(a0.x, a0.x), A0y = pk2(a0.y, a0.y);
        const unsigned long long A1x = pk2(a1.x, a1.x), A1y = pk2(a1.y, a1.y);
        const unsigned long long B0x = pk2(b0.x, b0.x), B0y = pk2(b0.y, b0.y);
        const unsigned long long B1x = pk2(b1.x, b1.x), B1y = pk2(b1.y, b1.y);
#pragma unroll
        for (int p = 0; p < P; p++) {
            const ulonglong2 xv = __ldg(&xp[p][kq]);   // (A,B)@2kq , (A,B)@2kq+1
            ag0[p] = fma2(A0x, xv.x, ag0[p]); ag0[p] = fma2(A0y, xv.y, ag0[p]);
            ag1[p] = fma2(A1x, xv.x, ag1[p]); ag1[p] = fma2(A1y, xv.y, ag1[p]);
            au0[p] = fma2(B0x, xv.x, au0[p]); au0[p] = fma2(B0y, xv.y, au0[p]);
            au1[p] = fma2(B1x, xv.x, au1[p]); au1[p] = fma2(B1y, xv.y, au1[p]);
        }
    }

#pragma unroll
    for (int p = 0; p < P; p++) {
#pragma unroll
        for (int o = 16; o > 0; o >>= 1) {
            ag0[p] = add2(ag0[p], __shfl_down_sync(0xFFFFFFFFu, ag0[p], o));
            ag1[p] = add2(ag1[p], __shfl_down_sync(0xFFFFFFFFu, ag1[p], o));
            au0[p] = add2(au0[p], __shfl_down_sync(0xFFFFFFFFu, au0[p], o));
            au1[p] = add2(au1[p], __shfl_down_sync(0xFFFFFFFFu, au1[p], o));
        }
        if (lane == 0 && 2 * p < nc) {
            float gA, gB, uA, uB;
            const int g = slot0 + 2 * p;   // even group
            upk2(ag0[p], gA, gB); upk2(au0[p], uA, uB);
            float* mo0 = d_mixed2 + (size_t)g * NI + 2 * i0;
            mo0[0] = (gA / (1.f + expf(-gA))) * uA;
            mo0[1] = (gB / (1.f + expf(-gB))) * uB;
            upk2(ag1[p], gA, gB); upk2(au1[p], uA, uB);
            float* mo1 = d_mixed2 + (size_t)g * NI + 2 * (i0 + 1);
            mo1[0] = (gA / (1.f + expf(-gA))) * uA;
            mo1[1] = (gB / (1.f + expf(-gB))) * uB;
        }
    }
}

__global__ void __launch_bounds__(128) gateup_kernel(
    const float* __restrict__ w_gate, const float* __restrict__ w_up)
{
    const int e = blockIdx.y;
    const int nT = d_expert_count[e];
    if (nT == 0) return;
    const int start = d_expert_start[e];   // even
    const int warp = threadIdx.x >> 5;
    const int lane = threadIdx.x & 31;
    const int i0 = blockIdx.x * 8 + warp * 2;   // 2 inter rows per warp

    const float2* G0 = (const float2*)(w_gate + ((size_t)e * NI + i0) * NH);
    const float2* G1 = (const float2*)(w_gate + ((size_t)e * NI + i0 + 1) * NH);
    const float2* U0 = (const float2*)(w_up   + ((size_t)e * NI + i0) * NH);
    const float2* U1 = (const float2*)(w_up   + ((size_t)e * NI + i0 + 1) * NH);

    for (int c = 0; c < nT; c += 8) {
        const int nc = (nT - c < 8) ? (nT - c) : 8;
        const int slot0 = start + c;   // even
        if      (nc <= 2) gateup_body<1>(nc, slot0, G0, G1, U0, U1, i0, lane);
        else if (nc <= 4) gateup_body<2>(nc, slot0, G0, G1, U0, U1, i0, lane);
        else if (nc <= 6) gateup_body<3>(nc, slot0, G0, G1, U0, U1, i0, lane);
        else              gateup_body<4>(nc, slot0, G0, G1, U0, U1, i0, lane);
    }
}

// ============================================================
// Kernel 3: down projection. One warp: 4 h-rows, P token-pairs,
// same dense 2-k-per-lane scheme.
// ============================================================
template<int P>
__device__ __forceinline__ void down_body(
    const int nc, const int slot0,
    const float2* __restrict__ R0, const float2* __restrict__ R1,
    const float2* __restrict__ R2, const float2* __restrict__ R3,
    const int h0, const int lane)
{
    constexpr int ITERS = NI / 2 / 32;   // 22

    unsigned long long a0[P], a1[P], a2[P], a3[P];
#pragma unroll
    for (int p = 0; p < P; p++) { a0[p] = 0ull; a1[p] = 0ull; a2[p] = 0ull; a3[p] = 0ull; }

    const ulonglong2* __restrict__ xp[P];
#pragma unroll
    for (int p = 0; p < P; p++)
        xp[p] = (const ulonglong2*)(d_mixed2 + (size_t)(slot0 + 2 * p) * NI);

#pragma unroll 4
    for (int it = 0; it < ITERS; it++) {
        const int kq = lane + 32 * it;
        const float2 v0 = __ldg(&R0[kq]);
        const float2 v1 = __ldg(&R1[kq]);
        const float2 v2 = __ldg(&R2[kq]);
        const float2 v3 = __ldg(&R3[kq]);
        const unsigned long long W0x = pk2(v0.x, v0.x), W0y = pk2(v0.y, v0.y);
        const unsigned long long W1x = pk2(v1.x, v1.x), W1y = pk2(v1.y, v1.y);
        const unsigned long long W2x = pk2(v2.x, v2.x), W2y = pk2(v2.y, v2.y);
        const unsigned long long W3x = pk2(v3.x, v3.x), W3y = pk2(v3.y, v3.y);
#pragma unroll
        for (int p = 0; p < P; p++) {
            const ulonglong2 xv = __ldg(&xp[p][kq]);
            a0[p] = fma2(W0x, xv.x, a0[p]); a0[p] = fma2(W0y, xv.y, a0[p]);
            a1[p] = fma2(W1x, xv.x, a1[p]); a1[p] = fma2(W1y, xv.y, a1[p]);
            a2[p] = fma2(W2x, xv.x, a2[p]); a2[p] = fma2(W2y, xv.y, a2[p]);
            a3[p] = fma2(W3x, xv.x, a3[p]); a3[p] = fma2(W3y, xv.y, a3[p]);
        }
    }

#pragma unroll
    for (int p = 0; p < P; p++) {
#pragma unroll
        for (int o = 16; o > 0; o >>= 1) {
            a0[p] = add2(a0[p], __shfl_down_sync(0xFFFFFFFFu, a0[p], o));
            a1[p] = add2(a1[p], __shfl_down_sync(0xFFFFFFFFu, a1[p], o));
            a2[p] = add2(a2[p], __shfl_down_sync(0xFFFFFFFFu, a2[p], o));
            a3[p] = add2(a3[p], __shfl_down_sync(0xFFFFFFFFu, a3[p], o));
        }
        if (lane == 0 && 2 * p < nc) {
            const int sA = slot0 + 2 * p;
            float vA, vB;
            float* poA = d_pair_out + (size_t)sA * NH + h0;
            float* poB = poA + NH;
            upk2(a0[p], vA, vB); poA[0] = vA; poB[0] = vB;
            upk2(a1[p], vA, vB); poA[1] = vA; poB[1] = vB;
            upk2(a2[p], vA, vB); poA[2] = vA; poB[2] = vB;
            upk2(a3[p], vA, vB); poA[3] = vA; poB[3] = vB;
        }
    }
}

__global__ void __launch_bounds__(128) down_kernel(const float* __restrict__ w_down)
{
    const int e = blockIdx.y;
    const int nT = d_expert_count[e];
    if (nT == 0) return;
    const int start = d_expert_start[e];
    const int warp = threadIdx.x >> 5;
    const int lane = threadIdx.x & 31;
    const int h0 = blockIdx.x * 16 + warp * 4;   // 4 hidden rows per warp

    const float2* R0 = (const float2*)(w_down + ((size_t)e * NH + h0) * NI);
    const float2* R1 = (const float2*)(w_down + ((size_t)e * NH + h0 + 1) * NI);
    const float2* R2 = (const float2*)(w_down + ((size_t)e * NH + h0 + 2) * NI);
    const float2* R3 = (const float2*)(w_down + ((size_t)e * NH + h0 + 3) * NI);

    for (int c = 0; c < nT; c += 8) {
        const int nc = (nT - c < 8) ? (nT - c) : 8;
        const int slot0 = start + c;
        if      (nc <= 2) down_body<1>(nc, slot0, R0, R1, R2, R3, h0, lane);
        else if (nc <= 4) down_body<2>(nc, slot0, R0, R1, R2, R3, h0, lane);
        else if (nc <= 6) down_body<3>(nc, slot0, R0, R1, R2, R3, h0, lane);
        else              down_body<4>(nc, slot0, R0, R1, R2, R3, h0, lane);
    }
}

// ============================================================
// Kernel 4: weighted combine of the 4 routed pair outputs.
// ============================================================
__global__ void combine_kernel(float* __restrict__ out)
{
    const int idx = blockIdx.x * blockDim.x + threadIdx.x;  // [0, NT*NH)
    const int t = idx / NH;
    const int h = idx - t * NH;
    float s = 0.f;
#pragma unroll
    for (int k = 0; k < NK; k++) {
        const int p = d_pair_idx[t * NK + k];
        s = fmaf(d_topk_w[t * NK + k], d_pair_out[(size_t)p * NH + h], s);
    }
    out[idx] = s;
}

// ============================================================
extern "C" void kernel_launch(void* const* d_in, const int* in_sizes, int n_in,
                              void* d_out, int out_size)
{
    const float* x      = (const float*)d_in[0];
    const float* logits = (const float*)d_in[1];
    const float* wg     = (const float*)d_in[2];
    const float* wu     = (const float*)d_in[3];
    const float* wd     = (const float*)d_in[4];
    float* out = (float*)d_out;

    route_kernel<<<1, NT>>>(logits);
    gather_kernel<<<MAXSLOT, 128>>>(x);
    gateup_kernel<<<dim3(NI / 8, NE), 128>>>(wg, wu);
    down_kernel<<<dim3(NH / 16, NE), 128>>>(wd);
    combine_kernel<<<(NT * NH) / 256, 256>>>(out);
}

// round 13
// speedup vs baseline: 1.3701x; 1.3701x over previous
#include <cuda_runtime.h>
#include <math.h>

#define NT 64
#define NH 2048
#define NI 1408
#define NE 32
#define NK 4
#define NPAIR (NT * NK)
#define MAXSLOT (NPAIR + NE)   // per-expert even padding adds <=1 slot each
#define MAXCHUNK 64            // sum ceil(cnt_e/8) <= 32 + 32

// ---- scratch (device globals: no allocation allowed) ----
__device__ int   d_expert_count[NE];
__device__ int   d_expert_start[NE];     // even per-expert starts
__device__ int   d_total_slots;
__device__ int   d_nchunks;
__device__ int   d_chunk_slot0[MAXCHUNK];        // chunk -> first slot (even)
__device__ int   d_chunk_nc[MAXCHUNK];           // chunk -> token count (1..8)
__device__ int   d_pair_token[MAXSLOT];          // slot -> token (pads -> 0)
__device__ int   d_pair_idx[NT * NK];            // (token,k) -> slot
__device__ float d_topk_w[NT * NK];              // routing weights
__device__ float d_xg2[(MAXSLOT + 2) * NH];      // x, token-PAIR interleaved: [g][k][2]
__device__ float d_mixed2[(MAXSLOT + 2) * NI];   // silu(g)*u, same interleaving
__device__ float d_pair_out[MAXSLOT * NH];       // down output per slot

// ---- packed f32x2 helpers (FFMA2: PTX-only on sm_103a) ----
__device__ __forceinline__ unsigned long long pk2(float lo, float hi) {
    unsigned long long r;
    asm("mov.b64 %0, {%1, %2};" : "=l"(r) : "f"(lo), "f"(hi));
    return r;
}
__device__ __forceinline__ void upk2(unsigned long long v, float& lo, float& hi) {
    asm("mov.b64 {%0, %1}, %2;" : "=f"(lo), "=f"(hi) : "l"(v));
}
__device__ __forceinline__ unsigned long long fma2(unsigned long long a,
                                                   unsigned long long b,
                                                   unsigned long long c) {
    unsigned long long d;
    asm("fma.rn.f32x2 %0, %1, %2, %3;" : "=l"(d) : "l"(a), "l"(b), "l"(c));
    return d;
}
__device__ __forceinline__ unsigned long long add2(unsigned long long a,
                                                   unsigned long long b) {
    unsigned long long d;
    asm("add.rn.f32x2 %0, %1, %2;" : "=l"(d) : "l"(a), "l"(b));
    return d;
}
// streaming float2 load (evict-first: keep L1 for activations)
__device__ __forceinline__ float2 ldcs2(const float2* p) {
    float2 v;
    asm("ld.global.cs.v2.f32 {%0, %1}, [%2];" : "=f"(v.x), "=f"(v.y) : "l"(p));
    return v;
}

// ============================================================
// Kernel 1: routing + chunk table. One block, one thread/token.
// ============================================================
__global__ void route_kernel(const float* __restrict__ logits) {
    __shared__ int s_count[NE];
    __shared__ int s_start[NE];
    __shared__ int s_slot[NE];
    const int t = threadIdx.x;

    if (t < NE) { s_count[t] = 0; s_slot[t] = 0; }
    __syncthreads();

    float v[NE];
#pragma unroll
    for (int e = 0; e < NE; e++) v[e] = logits[t * NE + e];

    int ids[NK];
    float vals[NK];
#pragma unroll
    for (int k = 0; k < NK; k++) {
        int best = 0;
        float bv = -1e30f;
#pragma unroll
        for (int e = 0; e < NE; e++) {
            if (v[e] > bv) { bv = v[e]; best = e; }  // strict > : lowest index wins ties
        }
        ids[k] = best;
        vals[k] = bv;
        v[best] = -1e30f;
    }

    float m = vals[0];
    float w[NK];
    float s = 0.f;
#pragma unroll
    for (int k = 0; k < NK; k++) { w[k] = expf(vals[k] - m); s += w[k]; }
    float inv = 1.f / s;
#pragma unroll
    for (int k = 0; k < NK; k++) d_topk_w[t * NK + k] = w[k] * inv;

#pragma unroll
    for (int k = 0; k < NK; k++) atomicAdd(&s_count[ids[k]], 1);
    __syncthreads();

    if (t == 0) {
        int off = 0;
        int nch = 0;
        for (int e = 0; e < NE; e++) {
            s_start[e] = off;
            const int cnt = s_count[e];
            for (int c = 0; c < cnt; c += 8) {            // chunk table
                d_chunk_slot0[nch] = off + c;
                d_chunk_nc[nch] = (cnt - c < 8) ? (cnt - c) : 8;
                nch++;
            }
            off += (cnt + 1) & ~1;   // pad each expert region to even
        }
        d_total_slots = off;
        d_nchunks = nch;
    }
    __syncthreads();

#pragma unroll
    for (int k = 0; k < NK; k++) {
        int slot = atomicAdd(&s_slot[ids[k]], 1);
        int p = s_start[ids[k]] + slot;
        d_pair_token[p] = t;
        d_pair_idx[t * NK + k] = p;
    }
    if (t < NE) {
        d_expert_count[t] = s_count[t];
        d_expert_start[t] = s_start[t];
        if (s_count[t] & 1)                  // fill the pad slot with token 0
            d_pair_token[s_start[t] + s_count[t]] = 0;
    }
}

// expert id for a slot (needed by flattened chunk blocks)
__device__ __forceinline__ int slot_expert(int slot0) {
    // linear scan over 32 experts (starts are sorted)
    int e = 0;
#pragma unroll
    for (int i = 1; i < NE; i++)
        if (d_expert_start[i] <= slot0 && d_expert_count[i] > 0) e = i;
    return e;
}

// ============================================================
// Kernel 1b: gather x rows, token-pair interleaved.
//   d_xg2[(p&~1)*NH + 2k + (p&1)] = x[token(p)][k]
// ============================================================
__global__ void gather_kernel(const float* __restrict__ x) {
    const int p = blockIdx.x;
    if (p >= d_total_slots) return;
    const int t = d_pair_token[p];
    const int g = p & ~1;
    const int par = p & 1;
    const float* __restrict__ src = x + (size_t)t * NH;
    float* __restrict__ dst = d_xg2 + (size_t)g * NH + par;
    for (int k = threadIdx.x; k < NH; k += blockDim.x)
        dst[2 * k] = src[k];
}

// ============================================================
// Kernel 2: gate/up matvecs + SiLU. One block = one chunk x 8
// inter rows. One warp: 2 inter rows (gate+up = 4 streams),
// P token-pairs in FFMA2 halves. Per-lane granularity 2 k:
// all loads stride-dense. Weights __ldcs (evict-first).
// ============================================================
template<int P>   // token pairs this chunk, 1..4
__device__ __forceinline__ void gateup_body(
    const int nc, const int slot0,
    const float2* __restrict__ G0, const float2* __restrict__ G1,
    const float2* __restrict__ U0, const float2* __restrict__ U1,
    const int i0, const int lane)
{
    constexpr int ITERS = NH / 2 / 32;   // 32

    unsigned long long ag0[P], ag1[P], au0[P], au1[P];
#pragma unroll
    for (int p = 0; p < P; p++) { ag0[p] = 0ull; ag1[p] = 0ull; au0[p] = 0ull; au1[p] = 0ull; }

    const ulonglong2* __restrict__ xp[P];
#pragma unroll
    for (int p = 0; p < P; p++)
        xp[p] = (const ulonglong2*)(d_xg2 + (size_t)(slot0 + 2 * p) * NH);

#pragma unroll 2
    for (int it = 0; it < ITERS; it++) {
        const int kq = lane + 32 * it;       // covers k = 2kq, 2kq+1
        const float2 a0 = ldcs2(&G0[kq]);
        const float2 a1 = ldcs2(&G1[kq]);
        const float2 b0 = ldcs2(&U0[kq]);
        const float2 b1 = ldcs2(&U1[kq]);
        const unsigned long long A0x = pk2(a0.x, a0.x), A0y = pk2(a0.y, a0.y);
        const unsigned long long A1x = pk2(a1.x, a1.x), A1y = pk2(a1.y, a1.y);
        const unsigned long long B0x = pk2(b0.x, b0.x), B0y = pk2(b0.y, b0.y);
        const unsigned long long B1x = pk2(b1.x, b1.x), B1y = pk2(b1.y, b1.y);
#pragma unroll
        for (int p = 0; p < P; p++) {
            const ulonglong2 xv = __ldg(&xp[p][kq]);   // (A,B)@2kq , (A,B)@2kq+1
            ag0[p] = fma2(A0x, xv.x, ag0[p]); ag0[p] = fma2(A0y, xv.y, ag0[p]);
            ag1[p] = fma2(A1x, xv.x, ag1[p]); ag1[p] = fma2(A1y, xv.y, ag1[p]);
            au0[p] = fma2(B0x, xv.x, au0[p]); au0[p] = fma2(B0y, xv.y, au0[p]);
            au1[p] = fma2(B1x, xv.x, au1[p]); au1[p] = fma2(B1y, xv.y, au1[p]);
        }
    }

#pragma unroll
    for (int p = 0; p < P; p++) {
#pragma unroll
        for (int o = 16; o > 0; o >>= 1) {
            ag0[p] = add2(ag0[p], __shfl_down_sync(0xFFFFFFFFu, ag0[p], o));
            ag1[p] = add2(ag1[p], __shfl_down_sync(0xFFFFFFFFu, ag1[p], o));
            au0[p] = add2(au0[p], __shfl_down_sync(0xFFFFFFFFu, au0[p], o));
            au1[p] = add2(au1[p], __shfl_down_sync(0xFFFFFFFFu, au1[p], o));
        }
        if (lane == 0 && 2 * p < nc) {
            float gA, gB, uA, uB;
            const int g = slot0 + 2 * p;   // even group
            upk2(ag0[p], gA, gB); upk2(au0[p], uA, uB);
            float* mo0 = d_mixed2 + (size_t)g * NI + 2 * i0;
            mo0[0] = (gA / (1.f + expf(-gA))) * uA;
            mo0[1] = (gB / (1.f + expf(-gB))) * uB;
            upk2(ag1[p], gA, gB); upk2(au1[p], uA, uB);
            float* mo1 = d_mixed2 + (size_t)g * NI + 2 * (i0 + 1);
            mo1[0] = (gA / (1.f + expf(-gA))) * uA;
            mo1[1] = (gB / (1.f + expf(-gB))) * uB;
        }
    }
}

__global__ void __launch_bounds__(128, 6) gateup_kernel(
    const float* __restrict__ w_gate, const float* __restrict__ w_up)
{
    const int ch = blockIdx.y;
    if (ch >= d_nchunks) return;
    const int slot0 = d_chunk_slot0[ch];
    const int nc = d_chunk_nc[ch];
    const int e = slot_expert(slot0);

    const int warp = threadIdx.x >> 5;
    const int lane = threadIdx.x & 31;
    const int i0 = blockIdx.x * 8 + warp * 2;   // 2 inter rows per warp

    const float2* G0 = (const float2*)(w_gate + ((size_t)e * NI + i0) * NH);
    const float2* G1 = (const float2*)(w_gate + ((size_t)e * NI + i0 + 1) * NH);
    const float2* U0 = (const float2*)(w_up   + ((size_t)e * NI + i0) * NH);
    const float2* U1 = (const float2*)(w_up   + ((size_t)e * NI + i0 + 1) * NH);

    if      (nc <= 2) gateup_body<1>(nc, slot0, G0, G1, U0, U1, i0, lane);
    else if (nc <= 4) gateup_body<2>(nc, slot0, G0, G1, U0, U1, i0, lane);
    else if (nc <= 6) gateup_body<3>(nc, slot0, G0, G1, U0, U1, i0, lane);
    else              gateup_body<4>(nc, slot0, G0, G1, U0, U1, i0, lane);
}

// ============================================================
// Kernel 3: down projection. One block = one chunk x 16 hidden
// rows. One warp: 4 h-rows, P token-pairs, dense 2-k-per-lane.
// ============================================================
template<int P>
__device__ __forceinline__ void down_body(
    const int nc, const int slot0,
    const float2* __restrict__ R0, const float2* __restrict__ R1,
    const float2* __restrict__ R2, const float2* __restrict__ R3,
    const int h0, const int lane)
{
    constexpr int ITERS = NI / 2 / 32;   // 22

    unsigned long long a0[P], a1[P], a2[P], a3[P];
#pragma unroll
    for (int p = 0; p < P; p++) { a0[p] = 0ull; a1[p] = 0ull; a2[p] = 0ull; a3[p] = 0ull; }

    const ulonglong2* __restrict__ xp[P];
#pragma unroll
    for (int p = 0; p < P; p++)
        xp[p] = (const ulonglong2*)(d_mixed2 + (size_t)(slot0 + 2 * p) * NI);

#pragma unroll 2
    for (int it = 0; it < ITERS; it++) {
        const int kq = lane + 32 * it;
        const float2 v0 = ldcs2(&R0[kq]);
        const float2 v1 = ldcs2(&R1[kq]);
        const float2 v2 = ldcs2(&R2[kq]);
        const float2 v3 = ldcs2(&R3[kq]);
        const unsigned long long W0x = pk2(v0.x, v0.x), W0y = pk2(v0.y, v0.y);
        const unsigned long long W1x = pk2(v1.x, v1.x), W1y = pk2(v1.y, v1.y);
        const unsigned long long W2x = pk2(v2.x, v2.x), W2y = pk2(v2.y, v2.y);
        const unsigned long long W3x = pk2(v3.x, v3.x), W3y = pk2(v3.y, v3.y);
#pragma unroll
        for (int p = 0; p < P; p++) {
            const ulonglong2 xv = __ldg(&xp[p][kq]);
            a0[p] = fma2(W0x, xv.x, a0[p]); a0[p] = fma2(W0y, xv.y, a0[p]);
            a1[p] = fma2(W1x, xv.x, a1[p]); a1[p] = fma2(W1y, xv.y, a1[p]);
            a2[p] = fma2(W2x, xv.x, a2[p]); a2[p] = fma2(W2y, xv.y, a2[p]);
            a3[p] = fma2(W3x, xv.x, a3[p]); a3[p] = fma2(W3y, xv.y, a3[p]);
        }
    }

#pragma unroll
    for (int p = 0; p < P; p++) {
#pragma unroll
        for (int o = 16; o > 0; o >>= 1) {
            a0[p] = add2(a0[p], __shfl_down_sync(0xFFFFFFFFu, a0[p], o));
            a1[p] = add2(a1[p], __shfl_down_sync(0xFFFFFFFFu, a1[p], o));
            a2[p] = add2(a2[p], __shfl_down_sync(0xFFFFFFFFu, a2[p], o));
            a3[p] = add2(a3[p], __shfl_down_sync(0xFFFFFFFFu, a3[p], o));
        }
        if (lane == 0 && 2 * p < nc) {
            const int sA = slot0 + 2 * p;
            float vA, vB;
            float* poA = d_pair_out + (size_t)sA * NH + h0;
            float* poB = poA + NH;
            upk2(a0[p], vA, vB); poA[0] = vA; poB[0] = vB;
            upk2(a1[p], vA, vB); poA[1] = vA; poB[1] = vB;
            upk2(a2[p], vA, vB); poA[2] = vA; poB[2] = vB;
            upk2(a3[p], vA, vB); poA[3] = vA; poB[3] = vB;
        }
    }
}

__global__ void __launch_bounds__(128, 6) down_kernel(const float* __restrict__ w_down)
{
    const int ch = blockIdx.y;
    if (ch >= d_nchunks) return;
    const int slot0 = d_chunk_slot0[ch];
    const int nc = d_chunk_nc[ch];
    const int e = slot_expert(slot0);

    const int warp = threadIdx.x >> 5;
    const int lane = threadIdx.x & 31;
    const int h0 = blockIdx.x * 16 + warp * 4;   // 4 hidden rows per warp

    const float2* R0 = (const float2*)(w_down + ((size_t)e * NH + h0) * NI);
    const float2* R1 = (const float2*)(w_down + ((size_t)e * NH + h0 + 1) * NI);
    const float2* R2 = (const float2*)(w_down + ((size_t)e * NH + h0 + 2) * NI);
    const float2* R3 = (const float2*)(w_down + ((size_t)e * NH + h0 + 3) * NI);

    if      (nc <= 2) down_body<1>(nc, slot0, R0, R1, R2, R3, h0, lane);
    else if (nc <= 4) down_body<2>(nc, slot0, R0, R1, R2, R3, h0, lane);
    else if (nc <= 6) down_body<3>(nc, slot0, R0, R1, R2, R3, h0, lane);
    else              down_body<4>(nc, slot0, R0, R1, R2, R3, h0, lane);
}

// ============================================================
// Kernel 4: weighted combine of the 4 routed pair outputs.
// ============================================================
__global__ void combine_kernel(float* __restrict__ out)
{
    const int idx = blockIdx.x * blockDim.x + threadIdx.x;  // [0, NT*NH)
    const int t = idx / NH;
    const int h = idx - t * NH;
    float s = 0.f;
#pragma unroll
    for (int k = 0; k < NK; k++) {
        const int p = d_pair_idx[t * NK + k];
        s = fmaf(d_topk_w[t * NK + k], d_pair_out[(size_t)p * NH + h], s);
    }
    out[idx] = s;
}

// ============================================================
extern "C" void kernel_launch(void* const* d_in, const int* in_sizes, int n_in,
                              void* d_out, int out_size)
{
    const float* x      = (const float*)d_in[0];
    const float* logits = (const float*)d_in[1];
    const float* wg     = (const float*)d_in[2];
    const float* wu     = (const float*)d_in[3];
    const float* wd     = (const float*)d_in[4];
    float* out = (float*)d_out;

    route_kernel<<<1, NT>>>(logits);
    gather_kernel<<<MAXSLOT, 128>>>(x);
    gateup_kernel<<<dim3(NI / 8, MAXCHUNK), 128>>>(wg, wu);
    down_kernel<<<dim3(NH / 16, MAXCHUNK), 128>>>(wd);
    combine_kernel<<<(NT * NH) / 256, 256>>>(out);
}